// round 8
// baseline (speedup 1.0000x reference)
#include <cuda_runtime.h>
#include <cstdint>

// ---------------------------------------------------------------------------
// RipsECC. B=4096 points in [0,1]^3, 64 bins, bin(d) = ceil(31.5*d) in [0,55].
// All C(4096,2)=8,386,560 pairs are edges. out = cumsum(+4096 at bin0 - hist).
//
// 64-WARPS/SM round: 296 blocks x 1024 threads, 2 CTAs/SM (100% occupancy).
// Points live in GLOBAL (L1-resident broadcast via __ldg) -> smem holds only
// the u8 histogram: [8 regions][64 bins][32 lanes] u32 words = 64 KB/CTA.
// 32 warps/CTA: region = warp>>2, byte bank = warp&3 (race-free byte stores,
// max 32 counts/slot). Units: per 32-row i-block b, 1 diagonal tile +
// (127-b) chunks of 32 j's; NUNITS = 8256 over 296*32 = 9472 warp slots.
// ---------------------------------------------------------------------------

#define NPTS      4096
#define NSTEPS    64
#define NTHREADS  1024
#define NBLOCKS   296
#define NUNITS    8256
#define NREGIONS  8
#define HIST_WORDS (NREGIONS * NSTEPS * 32)     // 16384 words = 64 KB
#define SMEM_BYTES (HIST_WORDS * 4)

__device__ float4   g_pts[NPTS];                // (x, y, z, 992.25*|p|^2)
__device__ int      g_part[NBLOCKS][NSTEPS];
__device__ unsigned g_ticket = 0;

// Prep: materialize float4 points with scaled squared norm (coalesced LDG.128).
__global__ void prep_kernel(const float* __restrict__ x) {
    const int t = threadIdx.x;                  // 1024 threads, 4 points each
    const float4* xv = (const float4*)x;        // 12288 floats = 3072 float4
    float4 v0 = xv[3 * t + 0];
    float4 v1 = xv[3 * t + 1];
    float4 v2 = xv[3 * t + 2];
    g_pts[4 * t + 0] = make_float4(v0.x, v0.y, v0.z,
        992.25f * fmaf(v0.x, v0.x, fmaf(v0.y, v0.y, v0.z * v0.z)));
    g_pts[4 * t + 1] = make_float4(v0.w, v1.x, v1.y,
        992.25f * fmaf(v0.w, v0.w, fmaf(v1.x, v1.x, v1.y * v1.y)));
    g_pts[4 * t + 2] = make_float4(v1.z, v1.w, v2.x,
        992.25f * fmaf(v1.z, v1.z, fmaf(v1.w, v1.w, v2.x * v2.x)));
    g_pts[4 * t + 3] = make_float4(v2.y, v2.z, v2.w,
        992.25f * fmaf(v2.y, v2.y, fmaf(v2.z, v2.z, v2.w * v2.w)));
}

// bin = ceil(31.5*d) = ceil(sqrt(m)); m = 992.25*d2 via norm expansion.
__device__ __forceinline__ int bin_of(float A, float B, float C, float K,
                                      float4 p) {
    float m = fmaf(A, p.x, fmaf(B, p.y, fmaf(C, p.z, K + p.w)));
    float d;
    asm("sqrt.approx.f32 %0, %1;" : "=f"(d) : "f"(m));   // MUFU.SQRT
    return __float2int_ru(d);                            // t in [0, 55]
}

__global__ void __launch_bounds__(NTHREADS, 2)
rips_ecc_kernel(float* __restrict__ out) {
    __shared__ unsigned hist[HIST_WORDS];       // [8][64][32] u32 words

    const int tid = threadIdx.x;

    uint4* h4 = (uint4*)hist;
    #pragma unroll
    for (int i = 0; i < HIST_WORDS / 4 / NTHREADS; i++)
        h4[i * NTHREADS + tid] = make_uint4(0u, 0u, 0u, 0u);
    __syncthreads();

    const int warp = tid >> 5;   // 0..31
    const int lane = tid & 31;
    // u8 slot: region = warp>>2 (8192 B each); byte = lane*4 + (warp&3).
    unsigned char* myh = (unsigned char*)hist + (warp >> 2) * 8192 +
                         lane * 4 + (warp & 3);

    const int u = warp * NBLOCKS + blockIdx.x;  // [0, 9472)
    if (u < NUNITS) {
        // prefix(b) = 128b - b(b-1)/2; b = (257 - sqrt(257^2 - 8u))/2, fixup.
        int b = (int)(0.5f * (257.0f - sqrtf((float)(66049 - 8 * u))));
        b = max(0, min(127, b));
        while (b > 0   && (128 * b - ((b * (b - 1)) >> 1)) > u) --b;
        while (b < 127 && (128 * (b + 1) - (((b + 1) * b) >> 1)) <= u) ++b;
        const int rem   = u - (128 * b - ((b * (b - 1)) >> 1));  // [0, 128-b)
        const int ibase = b << 5;

        float4 pi = __ldg(&g_pts[ibase + lane]);
        const float A = -1984.5f * pi.x;   // -2 * 992.25
        const float B = -1984.5f * pi.y;
        const float C = -1984.5f * pi.z;
        const float K = pi.w;

        if (rem == 0) {
            // Diagonal 32x32 tile: j = ibase+jj, count only jj > lane.
            #pragma unroll 4
            for (int jj = 1; jj < 32; jj++) {
                float4 p = __ldg(&g_pts[ibase + jj]);
                int t = bin_of(A, B, C, K, p);
                if (jj > lane)
                    myh[t << 7] += (unsigned char)1;
            }
        } else {
            // Off-diagonal chunk of 32 j's.
            const int j0 = ibase + 32 + ((rem - 1) << 5);
            #pragma unroll 4
            for (int jj = 0; jj < 32; jj++) {
                float4 p = __ldg(&g_pts[j0 + jj]);
                int t = bin_of(A, B, C, K, p);
                myh[t << 7] += (unsigned char)1;
            }
        }
    }
    __syncthreads();

    // Block reduction: warp w reduces bins {2w, 2w+1}; dp4a sums the 4
    // warp-banks per word across the 8 regions.
    #pragma unroll
    for (int bb = 0; bb < 2; bb++) {
        int bin = warp * 2 + bb;
        int s = 0;
        #pragma unroll
        for (int r = 0; r < NREGIONS; r++)
            s = __dp4a((int)hist[r * 2048 + (bin << 5) + lane], 0x01010101, s);
        #pragma unroll
        for (int o = 16; o > 0; o >>= 1)
            s += __shfl_down_sync(0xffffffffu, s, o);
        if (lane == 0)
            g_part[blockIdx.x][bin] = s;
    }
    __threadfence();
    __syncthreads();

    __shared__ int s_last;
    if (tid == 0)
        s_last = (atomicAdd(&g_ticket, 1u) == NBLOCKS - 1);
    __syncthreads();
    if (!s_last) return;
    __threadfence();

    // --- last block: reduce 296x64 partials, cumsum, write, reset ---
    __shared__ int red[NSTEPS * 16];
    {
        int bin = tid & 63;
        int grp = tid >> 6;               // 0..15
        int s = 0;
        for (int b2 = grp; b2 < NBLOCKS; b2 += 16)
            s += g_part[b2][bin];
        red[bin * 16 + grp] = s;
    }
    __syncthreads();
    __shared__ int ecc[NSTEPS];
    if (tid < NSTEPS) {
        int tot = 0;
        #pragma unroll
        for (int g = 0; g < 16; g++) tot += red[tid * 16 + g];
        ecc[tid] = (tid == 0 ? NPTS : 0) - tot;
    }
    __syncthreads();
    if (tid < 32) {
        int e0 = ecc[tid];
        int e1 = ecc[tid + 32];
        #pragma unroll
        for (int d = 1; d < 32; d <<= 1) {
            int t = __shfl_up_sync(0xffffffffu, e0, d);
            if (tid >= d) e0 += t;
        }
        int tot = __shfl_sync(0xffffffffu, e0, 31);
        #pragma unroll
        for (int d = 1; d < 32; d <<= 1) {
            int t = __shfl_up_sync(0xffffffffu, e1, d);
            if (tid >= d) e1 += t;
        }
        e1 += tot;
        out[tid]      = (float)e0;
        out[tid + 32] = (float)e1;
    }
    if (tid == 0) g_ticket = 0;   // self-reset for graph replay
}

extern "C" void kernel_launch(void* const* d_in, const int* in_sizes, int n_in,
                              void* d_out, int out_size) {
    (void)in_sizes; (void)n_in; (void)out_size;
    const float* x = (const float*)d_in[0];
    float* out = (float*)d_out;

    prep_kernel<<<1, NTHREADS>>>(x);
    rips_ecc_kernel<<<NBLOCKS, NTHREADS>>>(out);
}

// round 9
// speedup vs baseline: 1.3736x; 1.3736x over previous
#include <cuda_runtime.h>
#include <cstdint>

// ---------------------------------------------------------------------------
// RipsECC. B=4096 points in [0,1]^3, 64 bins, bin(d) = ceil(31.5*d) in [0,55].
// All C(4096,2)=8,386,560 pairs are edges. out = cumsum(+4096 at bin0 - hist).
//
// 148 blocks x 1024 threads (R4 chassis). Points stored PRESCALED by 31.5:
// pts[i] = (X,Y,Z, X^2+Y^2+Z^2), so m = (31.5 d)^2 = K_i + w_j - 2(Xi Xj+...).
// bin t = ceil(sqrt(m)) via MUFU.SQRT + magic-number round-up add (NO F2I:
// f = fadd.ru(d, 2^23) puts ceil(d) in the mantissa low bits).
// 2-i register blocking: 64-row superblocks s (lane owns i0 = 64s+lane,
// i1 = 64s+32+lane); units = 32-j chunks, prefix(s) = s(129-s), NUNITS=4160
// over 4736 warp slots. One broadcast LDS.128 serves 2 pairs.
// u16 histograms: warp-pair shares a u32 word (halfword stores, race-free),
// 16 regions x 64 bins x 32 lanes = 128 KB; max 64 counts/slot.
// ---------------------------------------------------------------------------

#define NPTS      4096
#define NSTEPS    64
#define NTHREADS  1024
#define NBLOCKS   148
#define NUNITS    4160
#define NREGIONS  16
#define HIST_WORDS (NREGIONS * NSTEPS * 32)        // 32768 words = 128 KB
#define SMEM_BYTES (NPTS * 16 + HIST_WORDS * 4)    // 64KB + 128KB = 196608 B
#define MAGIC     8388608.0f                       // 2^23

__device__ int      g_part[NBLOCKS][NSTEPS];
__device__ unsigned g_ticket = 0;

// d = sqrt(m) (MUFU), then halfword-index offset = ceil(d) << 6 without F2I.
__device__ __forceinline__ int bin_off(float A, float B, float C, float Kw,
                                       float4 p) {
    float m = fmaf(A, p.x, fmaf(B, p.y, fmaf(C, p.z, Kw)));
    float d;
    asm("sqrt.approx.f32 %0, %1;" : "=f"(d) : "f"(m));   // MUFU.SQRT
    float f = __fadd_ru(d, MAGIC);                       // mantissa lo = ceil(d)
    return (int)((__float_as_uint(f) & 63u) << 6);       // halfword index t*64
}

extern __shared__ float4 smem4[];

__global__ void __launch_bounds__(NTHREADS, 1)
rips_ecc_kernel(const float* __restrict__ x, float* __restrict__ out) {
    float4*   pts  = smem4;                       // [4096] (X,Y,Z, |P|^2), x31.5
    unsigned* hist = (unsigned*)(smem4 + NPTS);   // [16][64][32] u32 words

    const int tid = threadIdx.x;

    // Coalesced staging: thread t computes points 4t..4t+3 from 3 LDG.128,
    // prescaling by 31.5 and appending the squared norm.
    {
        const float4* xv = (const float4*)x;      // 12288 floats = 3072 float4
        float4 v0 = xv[3 * tid + 0];
        float4 v1 = xv[3 * tid + 1];
        float4 v2 = xv[3 * tid + 2];
        float px, py, pz;
        px = 31.5f * v0.x; py = 31.5f * v0.y; pz = 31.5f * v0.z;
        pts[4 * tid + 0] = make_float4(px, py, pz,
                                       fmaf(px, px, fmaf(py, py, pz * pz)));
        px = 31.5f * v0.w; py = 31.5f * v1.x; pz = 31.5f * v1.y;
        pts[4 * tid + 1] = make_float4(px, py, pz,
                                       fmaf(px, px, fmaf(py, py, pz * pz)));
        px = 31.5f * v1.z; py = 31.5f * v1.w; pz = 31.5f * v2.x;
        pts[4 * tid + 2] = make_float4(px, py, pz,
                                       fmaf(px, px, fmaf(py, py, pz * pz)));
        px = 31.5f * v2.y; py = 31.5f * v2.z; pz = 31.5f * v2.w;
        pts[4 * tid + 3] = make_float4(px, py, pz,
                                       fmaf(px, px, fmaf(py, py, pz * pz)));
    }
    uint4* h4 = (uint4*)hist;
    #pragma unroll
    for (int i = 0; i < HIST_WORDS / 4 / NTHREADS; i++)
        h4[i * NTHREADS + tid] = make_uint4(0u, 0u, 0u, 0u);
    __syncthreads();

    const int warp = tid >> 5;   // 0..31
    const int lane = tid & 31;
    // u16 bank: region = warp>>1 (8192 B each), halfword = lane*2 + (warp&1).
    unsigned short* myh = (unsigned short*)((char*)hist + (warp >> 1) * 8192)
                          + lane * 2 + (warp & 1);

    const int u = warp * NBLOCKS + blockIdx.x;    // [0, 4736)
    if (u < NUNITS) {
        // prefix(s) = s(129-s); s = (129 - sqrt(16641-4u))/2, fixup +-1.
        int s = (int)(0.5f * (129.0f - sqrtf((float)(16641 - 4 * u))));
        s = max(0, min(63, s));
        while (s > 0  && s * (129 - s) > u) --s;
        while (s < 63 && (s + 1) * (128 - s) <= u) ++s;
        const int rem   = u - s * (129 - s);      // [0, 128-2s)
        const int sbase = s << 6;

        float4 q0 = pts[sbase + lane];
        float4 q1 = pts[sbase + 32 + lane];
        const float A0 = -2.0f * q0.x, B0 = -2.0f * q0.y,
                    C0 = -2.0f * q0.z, K0 = q0.w;
        const float A1 = -2.0f * q1.x, B1 = -2.0f * q1.y,
                    C1 = -2.0f * q1.z, K1 = q1.w;

        if (rem < 2) {
            // Diagonal 64x64 tile half: jrel = 32*rem + jj; count (i_q, j)
            // only when jrel > 32q + lane.
            const int jr0 = rem << 5;
            #pragma unroll 4
            for (int jj = 0; jj < 32; jj++) {
                int jrel = jr0 + jj;
                float4 p = pts[sbase + jrel];
                int o0 = bin_off(A0, B0, C0, K0 + p.w, p);
                int o1 = bin_off(A1, B1, C1, K1 + p.w, p);
                if (jrel > lane)      myh[o0] += (unsigned short)1;
                if (jrel > lane + 32) myh[o1] += (unsigned short)1;
            }
        } else {
            // Off-diagonal chunk: 32 j's past the superblock.
            const int j0 = sbase + 64 + ((rem - 2) << 5);
            #pragma unroll 4
            for (int jj = 0; jj < 32; jj++) {
                float4 p = pts[j0 + jj];
                int o0 = bin_off(A0, B0, C0, K0 + p.w, p);
                int o1 = bin_off(A1, B1, C1, K1 + p.w, p);
                myh[o0] += (unsigned short)1;
                myh[o1] += (unsigned short)1;
            }
        }
    }
    __syncthreads();

    // Block reduction: warp w reduces bins {2w, 2w+1} across 16 regions;
    // each u32 word holds two halfword counters (lo+hi, sums < 64K).
    #pragma unroll
    for (int bb = 0; bb < 2; bb++) {
        int bin = warp * 2 + bb;
        unsigned sacc = 0;
        #pragma unroll
        for (int r = 0; r < NREGIONS; r++)
            sacc += hist[r * 2048 + (bin << 5) + lane];
        sacc = (sacc & 0xFFFFu) + (sacc >> 16);
        #pragma unroll
        for (int o = 16; o > 0; o >>= 1)
            sacc += __shfl_down_sync(0xffffffffu, sacc, o);
        if (lane == 0)
            g_part[blockIdx.x][bin] = (int)sacc;
    }
    __threadfence();
    __syncthreads();

    __shared__ int s_last;
    if (tid == 0)
        s_last = (atomicAdd(&g_ticket, 1u) == NBLOCKS - 1);
    __syncthreads();
    if (!s_last) return;
    __threadfence();

    // --- last block: reduce 148x64 partials, cumsum, write, reset ---
    __shared__ int red[NSTEPS * 16];
    {
        int bin = tid & 63;
        int grp = tid >> 6;               // 0..15
        int sacc = 0;
        for (int b2 = grp; b2 < NBLOCKS; b2 += 16)
            sacc += g_part[b2][bin];
        red[bin * 16 + grp] = sacc;
    }
    __syncthreads();
    __shared__ int ecc[NSTEPS];
    if (tid < NSTEPS) {
        int tot = 0;
        #pragma unroll
        for (int g = 0; g < 16; g++) tot += red[tid * 16 + g];
        ecc[tid] = (tid == 0 ? NPTS : 0) - tot;
    }
    __syncthreads();
    if (tid < 32) {
        int e0 = ecc[tid];
        int e1 = ecc[tid + 32];
        #pragma unroll
        for (int d = 1; d < 32; d <<= 1) {
            int t = __shfl_up_sync(0xffffffffu, e0, d);
            if (tid >= d) e0 += t;
        }
        int tot = __shfl_sync(0xffffffffu, e0, 31);
        #pragma unroll
        for (int d = 1; d < 32; d <<= 1) {
            int t = __shfl_up_sync(0xffffffffu, e1, d);
            if (tid >= d) e1 += t;
        }
        e1 += tot;
        out[tid]      = (float)e0;
        out[tid + 32] = (float)e1;
    }
    if (tid == 0) g_ticket = 0;   // self-reset for graph replay
}

extern "C" void kernel_launch(void* const* d_in, const int* in_sizes, int n_in,
                              void* d_out, int out_size) {
    (void)in_sizes; (void)n_in; (void)out_size;
    const float* x = (const float*)d_in[0];
    float* out = (float*)d_out;

    cudaFuncSetAttribute(rips_ecc_kernel,
                         cudaFuncAttributeMaxDynamicSharedMemorySize, SMEM_BYTES);

    rips_ecc_kernel<<<NBLOCKS, NTHREADS, SMEM_BYTES>>>(x, out);
}